// round 8
// baseline (speedup 1.0000x reference)
#include <cuda_runtime.h>

#define TSEQ 512
#define INF  14
#define HID  8

typedef unsigned long long ull;

__device__ __forceinline__ ull pk(float lo, float hi){
    ull r; asm("mov.b64 %0, {%1,%2};" : "=l"(r) : "f"(lo), "f"(hi)); return r;
}
__device__ __forceinline__ float2 upk(ull v){
    float2 r; asm("mov.b64 {%0,%1}, %2;" : "=f"(r.x), "=f"(r.y) : "l"(v)); return r;
}
__device__ __forceinline__ ull ffma2(ull a, ull b, ull c){
    ull d; asm("fma.rn.f32x2 %0, %1, %2, %3;" : "=l"(d) : "l"(a), "l"(b), "l"(c)); return d;
}
__device__ __forceinline__ float tanhx(float x){
    float r; asm("tanh.approx.f32 %0, %1;" : "=f"(r) : "f"(x)); return r;
}
__device__ __forceinline__ float sigx(float x){
    return fmaf(0.5f, tanhx(0.5f * x), 0.5f);
}

// 2 batch elements per warp, 16 lanes each: lane = eh*16 + p*8 + j.
// Each lane owns ALL 4 gate rows for h-index j but only HALF the k-range (p).
// Partial gate sums are merged with one shfl.xor(8)+add BEFORE activations;
// activations/cell state are computed redundantly (bitwise identically) in
// both halves. Same FLOPs per element as the 4-elem/warp mapping, but twice
// the warps for latency hiding.
__global__ __launch_bounds__(32, 14) void lstm_forex_kernel(
    const float* __restrict__ x,
    const float* __restrict__ Wih1, const float* __restrict__ Whh1,
    const float* __restrict__ bih1, const float* __restrict__ bhh1,
    const float* __restrict__ Wih2, const float* __restrict__ Whh2,
    const float* __restrict__ bih2, const float* __restrict__ bhh2,
    const float* __restrict__ bn_gamma, const float* __restrict__ bn_beta,
    const float* __restrict__ bn_mean, const float* __restrict__ bn_var,
    const float* __restrict__ w1, const float* __restrict__ b1,
    const float* __restrict__ w2, const float* __restrict__ b2,
    float* __restrict__ out, int Bn)
{
    const int lane  = threadIdx.x & 31;
    const int j     = lane & 7;
    const int p     = (lane >> 3) & 1;     // k-half
    const int gbase = lane & 16;           // element base lane
    const int e     = blockIdx.x * 2 + (lane >> 4);
    const bool valid = (e < Bn);
    const int ec = valid ? e : (Bn > 0 ? Bn - 1 : 0);
    const unsigned FULL = 0xffffffffu;

    // ---- packed per-lane weights: 4 gate rows, my k-half only ----
    // x pairs: p=0 -> pairs 0..3, p=1 -> pairs 3..6 with pair-3 weight zeroed
    ull wxp[4][4];     // Wih1
    ull wh1p[4][2];    // Whh1 pairs p*2, p*2+1
    ull wi2p[4][2];    // Wih2
    ull wh2p[4][2];    // Whh2
    ull ib1[4], ib2[4];  // accumulator inits (bias on p=0 only)
#pragma unroll
    for (int g = 0; g < 4; g++){
        const int row = g * 8 + j;
#pragma unroll
        for (int k = 0; k < 4; k++){
            const int pr = p * 3 + k;       // 0..3 or 3..6
            wxp[g][k] = pk(Wih1[row * 14 + 2*pr], Wih1[row * 14 + 2*pr + 1]);
        }
        if (p) wxp[g][0] = 0ull;            // avoid double-count of pair 3
#pragma unroll
        for (int k = 0; k < 2; k++){
            const int pr = p * 2 + k;
            wh1p[g][k] = pk(Whh1[row * 8 + 2*pr], Whh1[row * 8 + 2*pr + 1]);
            wi2p[g][k] = pk(Wih2[row * 8 + 2*pr], Wih2[row * 8 + 2*pr + 1]);
            wh2p[g][k] = pk(Whh2[row * 8 + 2*pr], Whh2[row * 8 + 2*pr + 1]);
        }
        ib1[g] = p ? 0ull : pk(bih1[row] + bhh1[row], 0.f);
        ib2[g] = p ? 0ull : pk(bih2[row] + bhh2[row], 0.f);
    }

    // x pointer: my element's row, my half's pairs (p*3 .. p*3+3)
    const ull* px = reinterpret_cast<const ull*>(x)
                  + (size_t)ec * (TSEQ * INF / 2) + p * 3;
    ull xb[4];
#pragma unroll
    for (int k = 0; k < 4; k++) xb[k] = px[k];
    px += 7;

    // packed recurrent operands for my k-half (2 pairs each), start at 0
    ull h1pk[2] = {0ull, 0ull};
    ull h2pk[2] = {0ull, 0ull};
    float c1 = 0.f, c2 = 0.f, h2 = 0.f;

#pragma unroll 1
    for (int t = 0; t < TSEQ; t++){
        // ---------------- layer 1: partial dots (my k-half) ----------------
        ull a0 = ib1[0], a1 = ib1[1], a2 = ib1[2], a3 = ib1[3];
#pragma unroll
        for (int k = 0; k < 4; k++){
            a0 = ffma2(wxp[0][k], xb[k], a0);
            a1 = ffma2(wxp[1][k], xb[k], a1);
            a2 = ffma2(wxp[2][k], xb[k], a2);
            a3 = ffma2(wxp[3][k], xb[k], a3);
        }
#pragma unroll
        for (int k = 0; k < 2; k++){
            a0 = ffma2(wh1p[0][k], h1pk[k], a0);
            a1 = ffma2(wh1p[1][k], h1pk[k], a1);
            a2 = ffma2(wh1p[2][k], h1pk[k], a2);
            a3 = ffma2(wh1p[3][k], h1pk[k], a3);
        }
        // prefetch x(t+1)
        if (t + 1 < TSEQ){
#pragma unroll
            for (int k = 0; k < 4; k++) xb[k] = px[k];
            px += 7;
        }
        // ---- merge halves (pre-activation) + activations ----
        float h1;
        {
            const float2 u0 = upk(a0), u1 = upk(a1), u2 = upk(a2), u3 = upk(a3);
            float s0 = u0.x + u0.y, s1 = u1.x + u1.y;
            float s2 = u2.x + u2.y, s3 = u3.x + u3.y;
            s0 += __shfl_xor_sync(FULL, s0, 8);
            s1 += __shfl_xor_sync(FULL, s1, 8);
            s2 += __shfl_xor_sync(FULL, s2, 8);
            s3 += __shfl_xor_sync(FULL, s3, 8);
            const float ai = sigx(s0), af = sigx(s1);
            const float ag = tanhx(s2), ao = sigx(s3);
            c1 = fmaf(af, c1, ai * ag);
            h1 = ao * tanhx(c1);
        }
        // ---- broadcast h1 pairs for my k-half (sources in p=0 sub-warp) ----
#pragma unroll
        for (int k = 0; k < 2; k++){
            const int jj = 4*p + 2*k;
            const float ha = __shfl_sync(FULL, h1, gbase + jj);
            const float hb = __shfl_sync(FULL, h1, gbase + jj + 1);
            h1pk[k] = pk(ha, hb);
        }
        // ---------------- layer 2: partial dots (my k-half) ----------------
        ull b0 = ib2[0], b1a = ib2[1], b2a = ib2[2], b3 = ib2[3];
#pragma unroll
        for (int k = 0; k < 2; k++){
            b0  = ffma2(wh2p[0][k], h2pk[k], b0);
            b1a = ffma2(wh2p[1][k], h2pk[k], b1a);
            b2a = ffma2(wh2p[2][k], h2pk[k], b2a);
            b3  = ffma2(wh2p[3][k], h2pk[k], b3);
        }
#pragma unroll
        for (int k = 0; k < 2; k++){
            b0  = ffma2(wi2p[0][k], h1pk[k], b0);
            b1a = ffma2(wi2p[1][k], h1pk[k], b1a);
            b2a = ffma2(wi2p[2][k], h1pk[k], b2a);
            b3  = ffma2(wi2p[3][k], h1pk[k], b3);
        }
        {
            const float2 u0 = upk(b0), u1 = upk(b1a), u2 = upk(b2a), u3 = upk(b3);
            float s0 = u0.x + u0.y, s1 = u1.x + u1.y;
            float s2 = u2.x + u2.y, s3 = u3.x + u3.y;
            s0 += __shfl_xor_sync(FULL, s0, 8);
            s1 += __shfl_xor_sync(FULL, s1, 8);
            s2 += __shfl_xor_sync(FULL, s2, 8);
            s3 += __shfl_xor_sync(FULL, s3, 8);
            const float ai = sigx(s0), af = sigx(s1);
            const float ag = tanhx(s2), ao = sigx(s3);
            c2 = fmaf(af, c2, ai * ag);
            h2 = ao * tanhx(c2);
        }
        // ---- broadcast h2 pairs for next step (off critical path) ----
#pragma unroll
        for (int k = 0; k < 2; k++){
            const int jj = 4*p + 2*k;
            const float ha = __shfl_sync(FULL, h2, gbase + jj);
            const float hb = __shfl_sync(FULL, h2, gbase + jj + 1);
            h2pk[k] = pk(ha, hb);
        }
    }

    // ---------------- epilogue: BatchNorm (eval) + MLP head ----------------
    const float scale = bn_gamma[j] * rsqrtf(bn_var[j] + 1e-5f);
    const float nrm   = fmaf(h2 - bn_mean[j], scale, bn_beta[j]);

    float p0 = w1[0 * 8 + j] * nrm;
    float p1 = w1[1 * 8 + j] * nrm;
    float p2 = w1[2 * 8 + j] * nrm;
    float p3 = w1[3 * 8 + j] * nrm;
#pragma unroll
    for (int off = 4; off > 0; off >>= 1){   // reduce within 8-lane subgroup
        p0 += __shfl_xor_sync(FULL, p0, off);
        p1 += __shfl_xor_sync(FULL, p1, off);
        p2 += __shfl_xor_sync(FULL, p2, off);
        p3 += __shfl_xor_sync(FULL, p3, off);
    }
    if (valid && (lane & 15) == 0){
        float o = b2[0];
        o = fmaf(w2[0], fmaxf(p0 + b1[0], 0.f), o);
        o = fmaf(w2[1], fmaxf(p1 + b1[1], 0.f), o);
        o = fmaf(w2[2], fmaxf(p2 + b1[2], 0.f), o);
        o = fmaf(w2[3], fmaxf(p3 + b1[3], 0.f), o);
        out[e] = o;
    }
}

extern "C" void kernel_launch(void* const* d_in, const int* in_sizes, int n_in,
                              void* d_out, int out_size)
{
    const float* x        = (const float*)d_in[0];
    const float* Wih1     = (const float*)d_in[1];
    const float* Whh1     = (const float*)d_in[2];
    const float* bih1     = (const float*)d_in[3];
    const float* bhh1     = (const float*)d_in[4];
    const float* Wih2     = (const float*)d_in[5];
    const float* Whh2     = (const float*)d_in[6];
    const float* bih2     = (const float*)d_in[7];
    const float* bhh2     = (const float*)d_in[8];
    const float* bn_gamma = (const float*)d_in[9];
    const float* bn_beta  = (const float*)d_in[10];
    const float* bn_mean  = (const float*)d_in[11];
    const float* bn_var   = (const float*)d_in[12];
    const float* w1       = (const float*)d_in[13];
    const float* b1       = (const float*)d_in[14];
    const float* w2       = (const float*)d_in[15];
    const float* b2       = (const float*)d_in[16];

    const int Bn = in_sizes[0] / (TSEQ * INF);
    const int grid = (Bn + 1) / 2;            // 2 batch elements per warp

    lstm_forex_kernel<<<grid, 32>>>(x, Wih1, Whh1, bih1, bhh1,
                                    Wih2, Whh2, bih2, bhh2,
                                    bn_gamma, bn_beta, bn_mean, bn_var,
                                    w1, b1, w2, b2,
                                    (float*)d_out, Bn);
}

// round 9
// speedup vs baseline: 1.2937x; 1.2937x over previous
#include <cuda_runtime.h>

#define TSEQ 512
#define INF  14
#define HID  8

typedef unsigned long long ull;

__device__ __forceinline__ ull pk(float lo, float hi){
    ull r; asm("mov.b64 %0, {%1,%2};" : "=l"(r) : "f"(lo), "f"(hi)); return r;
}
__device__ __forceinline__ float2 upk(ull v){
    float2 r; asm("mov.b64 {%0,%1}, %2;" : "=f"(r.x), "=f"(r.y) : "l"(v)); return r;
}
__device__ __forceinline__ ull ffma2(ull a, ull b, ull c){
    ull d; asm("fma.rn.f32x2 %0, %1, %2, %3;" : "=l"(d) : "l"(a), "l"(b), "l"(c)); return d;
}
__device__ __forceinline__ float tanhx(float x){
    float r; asm("tanh.approx.f32 %0, %1;" : "=f"(r) : "f"(x)); return r;
}
__device__ __forceinline__ float sigx(float x){
    return fmaf(0.5f, tanhx(0.5f * x), 0.5f);
}

// 4 batch elements per warp (8 lanes each); lane owns h-index j, all 4 gate rows.
// R7 structure (single shuffle of h1/h2 per step, L2 h2-partial hoisted) plus a
// DEPTH-2 x prefetch pipeline: the LDG for x(t+2) is issued right after x(t) is
// consumed, giving ~2 steps of latency cover so the x stream never sits on the
// recurrence critical path.
__global__ __launch_bounds__(32) void lstm_forex_kernel(
    const float* __restrict__ x,
    const float* __restrict__ Wih1, const float* __restrict__ Whh1,
    const float* __restrict__ bih1, const float* __restrict__ bhh1,
    const float* __restrict__ Wih2, const float* __restrict__ Whh2,
    const float* __restrict__ bih2, const float* __restrict__ bhh2,
    const float* __restrict__ bn_gamma, const float* __restrict__ bn_beta,
    const float* __restrict__ bn_mean, const float* __restrict__ bn_var,
    const float* __restrict__ w1, const float* __restrict__ b1,
    const float* __restrict__ w2, const float* __restrict__ b2,
    float* __restrict__ out, int Bn)
{
    const int lane = threadIdx.x & 31;
    const int j    = lane & 7;
    const int base = lane & 24;
    const int e    = blockIdx.x * 4 + (lane >> 3);
    const bool valid = (e < Bn);
    const int ec = valid ? e : (Bn > 0 ? Bn - 1 : 0);
    const unsigned FULL = 0xffffffffu;

    // ---- packed per-lane weights (gate rows j, j+8, j+16, j+24) ----
    ull wxp[4][7];    // (Wih1[row][2k], Wih1[row][2k+1])
    ull wh1p[4][4];   // (Whh1[row][2k], Whh1[row][2k+1])
    ull wi2p[4][4];   // (Wih2[row][2k], Wih2[row][2k+1])
    ull wh2p[4][4];   // (Whh2[row][2k], Whh2[row][2k+1])
    ull pb1[4], pb2[4];
#pragma unroll
    for (int g = 0; g < 4; g++){
        const int row = g * 8 + j;
#pragma unroll
        for (int k = 0; k < 7; k++)
            wxp[g][k] = pk(Wih1[row * 14 + 2*k], Wih1[row * 14 + 2*k + 1]);
#pragma unroll
        for (int k = 0; k < 4; k++){
            wh1p[g][k] = pk(Whh1[row * 8 + 2*k], Whh1[row * 8 + 2*k + 1]);
            wi2p[g][k] = pk(Wih2[row * 8 + 2*k], Wih2[row * 8 + 2*k + 1]);
            wh2p[g][k] = pk(Whh2[row * 8 + 2*k], Whh2[row * 8 + 2*k + 1]);
        }
        pb1[g] = pk(bih1[row] + bhh1[row], 0.f);
        pb2[g] = pk(bih2[row] + bhh2[row], 0.f);
    }

    // x[e, t, :]: 14 floats = 7 packed pairs; depth-2 double buffer
    const ull* px = reinterpret_cast<const ull*>(x) + (size_t)ec * (TSEQ * INF / 2);
    ull xb[2][7];
#pragma unroll
    for (int k = 0; k < 7; k++) xb[0][k] = px[k];        // x(0)
#pragma unroll
    for (int k = 0; k < 7; k++) xb[1][k] = px[7 + k];    // x(1)
    px += 14;                                            // -> x(2)

    // packed broadcast state: h1p[k] = (h1[2k], h1[2k+1]); same for h2p
    ull h1p[4] = {0ull,0ull,0ull,0ull};
    ull h2p[4] = {0ull,0ull,0ull,0ull};
    float c1 = 0.f, c2 = 0.f, h2 = 0.f;

#pragma unroll 2
    for (int t = 0; t < TSEQ; t++){
        ull* cur = xb[t & 1];

        // ---- L2 partial: bias + Whh2·h2(t-1)  (independent of L1 chain) ----
        ull aA0 = pb2[0], aA1 = pb2[1], aA2 = pb2[2], aA3 = pb2[3];
#pragma unroll
        for (int k = 0; k < 4; k++){
            aA0 = ffma2(wh2p[0][k], h2p[k], aA0);
            aA1 = ffma2(wh2p[1][k], h2p[k], aA1);
            aA2 = ffma2(wh2p[2][k], h2p[k], aA2);
            aA3 = ffma2(wh2p[3][k], h2p[k], aA3);
        }

        // ---- L1: x-dot (consume cur) + recurrent dot ----
        ull aB0 = pb1[0], aB1 = pb1[1], aB2 = pb1[2], aB3 = pb1[3];
#pragma unroll
        for (int k = 0; k < 7; k++){
            aB0 = ffma2(wxp[0][k], cur[k], aB0);
            aB1 = ffma2(wxp[1][k], cur[k], aB1);
            aB2 = ffma2(wxp[2][k], cur[k], aB2);
            aB3 = ffma2(wxp[3][k], cur[k], aB3);
        }
        // cur is free: issue LDG for x(t+2) NOW (~2 steps of latency cover)
        if (t + 2 < TSEQ){
#pragma unroll
            for (int k = 0; k < 7; k++) cur[k] = px[k];
            px += 7;
        }
#pragma unroll
        for (int k = 0; k < 4; k++){
            aB0 = ffma2(wh1p[0][k], h1p[k], aB0);
            aB1 = ffma2(wh1p[1][k], h1p[k], aB1);
            aB2 = ffma2(wh1p[2][k], h1p[k], aB2);
            aB3 = ffma2(wh1p[3][k], h1p[k], aB3);
        }
        // ---- L1 activations -> h1(t) ----
        float h1;
        {
            const float2 u0 = upk(aB0), u1 = upk(aB1), u2 = upk(aB2), u3 = upk(aB3);
            const float ai = sigx(u0.x + u0.y);
            const float af = sigx(u1.x + u1.y);
            const float ag = tanhx(u2.x + u2.y);
            const float ao = sigx(u3.x + u3.y);
            c1 = fmaf(af, c1, ai * ag);
            h1 = ao * tanhx(c1);
        }
        // ---- shuffle h1 ONCE; pairs feed L2(t) now and L1(t+1) next iter ----
#pragma unroll
        for (int k = 0; k < 4; k++){
            const float ha = __shfl_sync(FULL, h1, base + 2*k);
            const float hb = __shfl_sync(FULL, h1, base + 2*k + 1);
            h1p[k] = pk(ha, hb);
        }
        // ---- L2: + Wih2·h1(t), activations -> h2(t) ----
#pragma unroll
        for (int k = 0; k < 4; k++){
            aA0 = ffma2(wi2p[0][k], h1p[k], aA0);
            aA1 = ffma2(wi2p[1][k], h1p[k], aA1);
            aA2 = ffma2(wi2p[2][k], h1p[k], aA2);
            aA3 = ffma2(wi2p[3][k], h1p[k], aA3);
        }
        {
            const float2 u0 = upk(aA0), u1 = upk(aA1), u2 = upk(aA2), u3 = upk(aA3);
            const float ai = sigx(u0.x + u0.y);
            const float af = sigx(u1.x + u1.y);
            const float ag = tanhx(u2.x + u2.y);
            const float ao = sigx(u3.x + u3.y);
            c2 = fmaf(af, c2, ai * ag);
            h2 = ao * tanhx(c2);
        }
        // ---- shuffle h2 ONCE; pairs feed next iteration's L2 partial ----
#pragma unroll
        for (int k = 0; k < 4; k++){
            const float ha = __shfl_sync(FULL, h2, base + 2*k);
            const float hb = __shfl_sync(FULL, h2, base + 2*k + 1);
            h2p[k] = pk(ha, hb);
        }
    }

    // ---------------- epilogue: BatchNorm (eval) + MLP head ----------------
    const float scale = bn_gamma[j] * rsqrtf(bn_var[j] + 1e-5f);
    const float nrm   = fmaf(h2 - bn_mean[j], scale, bn_beta[j]);

    float p0 = w1[0 * 8 + j] * nrm;
    float p1 = w1[1 * 8 + j] * nrm;
    float p2 = w1[2 * 8 + j] * nrm;
    float p3 = w1[3 * 8 + j] * nrm;
#pragma unroll
    for (int off = 4; off > 0; off >>= 1){
        p0 += __shfl_xor_sync(FULL, p0, off);
        p1 += __shfl_xor_sync(FULL, p1, off);
        p2 += __shfl_xor_sync(FULL, p2, off);
        p3 += __shfl_xor_sync(FULL, p3, off);
    }
    if (valid && j == 0){
        float o = b2[0];
        o = fmaf(w2[0], fmaxf(p0 + b1[0], 0.f), o);
        o = fmaf(w2[1], fmaxf(p1 + b1[1], 0.f), o);
        o = fmaf(w2[2], fmaxf(p2 + b1[2], 0.f), o);
        o = fmaf(w2[3], fmaxf(p3 + b1[3], 0.f), o);
        out[e] = o;
    }
}

extern "C" void kernel_launch(void* const* d_in, const int* in_sizes, int n_in,
                              void* d_out, int out_size)
{
    const float* x        = (const float*)d_in[0];
    const float* Wih1     = (const float*)d_in[1];
    const float* Whh1     = (const float*)d_in[2];
    const float* bih1     = (const float*)d_in[3];
    const float* bhh1     = (const float*)d_in[4];
    const float* Wih2     = (const float*)d_in[5];
    const float* Whh2     = (const float*)d_in[6];
    const float* bih2     = (const float*)d_in[7];
    const float* bhh2     = (const float*)d_in[8];
    const float* bn_gamma = (const float*)d_in[9];
    const float* bn_beta  = (const float*)d_in[10];
    const float* bn_mean  = (const float*)d_in[11];
    const float* bn_var   = (const float*)d_in[12];
    const float* w1       = (const float*)d_in[13];
    const float* b1       = (const float*)d_in[14];
    const float* w2       = (const float*)d_in[15];
    const float* b2       = (const float*)d_in[16];

    const int Bn = in_sizes[0] / (TSEQ * INF);
    const int grid = (Bn + 3) / 4;            // 4 batch elements per warp, 1 warp/block

    lstm_forex_kernel<<<grid, 32>>>(x, Wih1, Whh1, bih1, bhh1,
                                    Wih2, Whh2, bih2, bhh2,
                                    bn_gamma, bn_beta, bn_mean, bn_var,
                                    w1, b1, w2, b2,
                                    (float*)d_out, Bn);
}